// round 6
// baseline (speedup 1.0000x reference)
#include <cuda_runtime.h>

#define BT     4096      // B*T
#define KCAND  64
#define DK     128
#define DCTX   256
#define DV     128
#define GAMMA  1.0f
#define ETA    1.0f
#define INV_TEMP 1.0f

#define CHUNK   8        // candidates per pipeline stage
#define NCHUNK  8        // KCAND / CHUNK
#define STAGE_F 5120     // floats per stage: K 1024 + ctx 2048 + rel 1024 + ent 1024
#define SMEM_FLOATS (2*STAGE_F + KCAND*DV + DK + DCTX + KCAND + 4*KCAND)
#define SMEM_BYTES  (SMEM_FLOATS * 4)   // 76544 B

#define QW_BLOCKS 128
#define QW_ROWS   32     // rows of Qw per producer block

// Qw scratch + handshake state. Flags/counters are zero at load and are
// returned to zero by the last consumer of each group every launch, so every
// graph replay sees identical initial state (no caching, fully deterministic).
__device__ float    g_qw[BT * DCTX];
__device__ unsigned g_flag[QW_BLOCKS];
__device__ unsigned g_cnt[QW_BLOCKS];

#define CP_ASYNC_CG16(dst, src) \
    asm volatile("cp.async.cg.shared.global [%0], [%1], 16;\n" :: "r"(dst), "l"(src))
#define CP_ASYNC_COMMIT() asm volatile("cp.async.commit_group;\n" ::)
#define CP_ASYNC_WAIT(N)  asm volatile("cp.async.wait_group %0;\n" :: "n"(N))

__device__ __forceinline__ unsigned smem_u32(const void* p) {
    return (unsigned)__cvta_generic_to_shared(p);
}

// ---------------------------------------------------------------------------
// Producer path: Qw[rows 32b..32b+31] = Q @ W_ctx.
// Register-tiled 4 rows x 8 cols outer product; ~91% FFMA density.
// ---------------------------------------------------------------------------
__device__ void qw_producer(float* smem,
                            const float* __restrict__ Q,
                            const float* __restrict__ W_ctx) {
    float* qsh = smem;                 // transposed Q: [128][36] padded
    const int tid = threadIdx.x;
    const int b   = blockIdx.x;
    const int rowbase = b * QW_ROWS;

#pragma unroll
    for (int i = 0; i < 16; ++i) {
        const int idx = tid + i * 256;      // 0..4095
        const int r = idx >> 7;             // 0..31
        const int d = idx & 127;
        qsh[d * 36 + r] = Q[(long)(rowbase + r) * DK + d];
    }
    __syncthreads();

    const int rg = tid >> 5;                // row group: rows rg*4..+3
    const int cq = (tid & 31) * 2;          // float4 col index: cols cq*4..cq*4+7
    const float4* W4 = (const float4*)W_ctx;

    float4 a00 = make_float4(0.f,0.f,0.f,0.f), a01 = a00;
    float4 a10 = a00, a11 = a00, a20 = a00, a21 = a00, a30 = a00, a31 = a00;

#pragma unroll 2
    for (int d = 0; d < DK; ++d) {
        const float4 q4 = *(const float4*)(qsh + d * 36 + rg * 4);  // broadcast
        const float4 w0 = W4[d * 64 + cq];
        const float4 w1 = W4[d * 64 + cq + 1];
        a00.x = fmaf(q4.x, w0.x, a00.x); a00.y = fmaf(q4.x, w0.y, a00.y);
        a00.z = fmaf(q4.x, w0.z, a00.z); a00.w = fmaf(q4.x, w0.w, a00.w);
        a01.x = fmaf(q4.x, w1.x, a01.x); a01.y = fmaf(q4.x, w1.y, a01.y);
        a01.z = fmaf(q4.x, w1.z, a01.z); a01.w = fmaf(q4.x, w1.w, a01.w);
        a10.x = fmaf(q4.y, w0.x, a10.x); a10.y = fmaf(q4.y, w0.y, a10.y);
        a10.z = fmaf(q4.y, w0.z, a10.z); a10.w = fmaf(q4.y, w0.w, a10.w);
        a11.x = fmaf(q4.y, w1.x, a11.x); a11.y = fmaf(q4.y, w1.y, a11.y);
        a11.z = fmaf(q4.y, w1.z, a11.z); a11.w = fmaf(q4.y, w1.w, a11.w);
        a20.x = fmaf(q4.z, w0.x, a20.x); a20.y = fmaf(q4.z, w0.y, a20.y);
        a20.z = fmaf(q4.z, w0.z, a20.z); a20.w = fmaf(q4.z, w0.w, a20.w);
        a21.x = fmaf(q4.z, w1.x, a21.x); a21.y = fmaf(q4.z, w1.y, a21.y);
        a21.z = fmaf(q4.z, w1.z, a21.z); a21.w = fmaf(q4.z, w1.w, a21.w);
        a30.x = fmaf(q4.w, w0.x, a30.x); a30.y = fmaf(q4.w, w0.y, a30.y);
        a30.z = fmaf(q4.w, w0.z, a30.z); a30.w = fmaf(q4.w, w0.w, a30.w);
        a31.x = fmaf(q4.w, w1.x, a31.x); a31.y = fmaf(q4.w, w1.y, a31.y);
        a31.z = fmaf(q4.w, w1.z, a31.z); a31.w = fmaf(q4.w, w1.w, a31.w);
    }

    {
        float4* o0 = (float4*)(g_qw + (long)(rowbase + rg * 4 + 0) * DCTX);
        float4* o1 = (float4*)(g_qw + (long)(rowbase + rg * 4 + 1) * DCTX);
        float4* o2 = (float4*)(g_qw + (long)(rowbase + rg * 4 + 2) * DCTX);
        float4* o3 = (float4*)(g_qw + (long)(rowbase + rg * 4 + 3) * DCTX);
        o0[cq] = a00; o0[cq + 1] = a01;
        o1[cq] = a10; o1[cq + 1] = a11;
        o2[cq] = a20; o2[cq + 1] = a21;
        o3[cq] = a30; o3[cq + 1] = a31;
    }
    __threadfence();       // each thread's stores visible gpu-wide
    __syncthreads();       // all threads done before release
    if (tid == 0) atomicExch(&g_flag[b], 1u);
}

// ---------------------------------------------------------------------------
// Fused kernel: blocks [0,128) produce Qw; blocks [128, 128+BT) are the
// per-row streaming consumers (R4 main path + flag wait).
// ---------------------------------------------------------------------------
__global__ __launch_bounds__(256) void kb_kernel(
    const float* __restrict__ Q,
    const float* __restrict__ K_kb,
    const float* __restrict__ V_kb,
    const float* __restrict__ ctx,
    const float* __restrict__ W_ctx,
    const float* __restrict__ b_ctx,
    const float* __restrict__ rel_emb,
    const float* __restrict__ ent_emb,
    const float* __restrict__ q_min,
    const float* __restrict__ q_max,
    const float* __restrict__ tau_min,
    const float* __restrict__ tau_max,
    const int*   __restrict__ rel_id,
    const int*   __restrict__ ent_id,
    float* __restrict__ out_alpha,
    float* __restrict__ out_v)
{
    extern __shared__ float smem[];

    if (blockIdx.x < QW_BLOCKS) {
        qw_producer(smem, Q, W_ctx);
        return;
    }

    float* sA    = smem;                         // [2][STAGE_F] stages
    float* sV    = smem + 2 * STAGE_F;           // [64][128]
    float* sQ    = sV + KCAND * DV;              // 128
    float* sQW   = sQ + DK;                      // 256
    float* sS    = sQW + DCTX;                   // 64 scores -> alpha
    int*   sRid  = (int*)(sS + KCAND);           // 64
    int*   sEid  = sRid + KCAND;                 // 64
    float* sTmin = (float*)(sEid + KCAND);       // 64
    float* sTmax = sTmin + KCAND;                // 64

    const int row  = blockIdx.x - QW_BLOCKS;
    const int tid  = threadIdx.x;
    const int warp = tid >> 5;
    const int lane = tid & 31;

    const long base_k = (long)row * KCAND * DK;
    const long base_c = (long)row * KCAND * DCTX;

    // ---- prologue: small per-row data ----
    if (tid < 64)        sRid [tid]       = rel_id [row * KCAND + tid];
    else if (tid < 128)  sEid [tid - 64]  = ent_id [row * KCAND + tid - 64];
    else if (tid < 192)  sTmin[tid - 128] = tau_min[row * KCAND + tid - 128];
    else                 sTmax[tid - 192] = tau_max[row * KCAND + tid - 192];
    if (tid < DK) sQ[tid] = Q[(long)row * DK + tid];
    __syncthreads();    // ids (cp.async addresses) + sQ visible

    // ---- chunk issuer: K+ctx+rel+ent stage (20KB) + V slice (4KB), 1 group
    auto issue_chunk = [&](int c, int stg) {
        const int kc = c * CHUNK;
        const unsigned dst = smem_u32(sA + stg * STAGE_F);
        { const int cand = tid >> 5, off = tid & 31;                     // K
          CP_ASYNC_CG16(dst + tid * 16,
                        K_kb + base_k + (long)(kc + cand) * DK + off * 4); }
        { const int cand = tid >> 6, off = tid & 63;                     // ctx lo
          CP_ASYNC_CG16(dst + (256 + tid) * 16,
                        ctx + base_c + (long)(kc + cand) * DCTX + off * 4); }
        { const int t = tid + 256; const int cand = t >> 6, off = t & 63; // ctx hi
          CP_ASYNC_CG16(dst + (256 + t) * 16,
                        ctx + base_c + (long)(kc + cand) * DCTX + off * 4); }
        { const int cand = tid >> 5, off = tid & 31;                     // rel
          CP_ASYNC_CG16(dst + (768 + tid) * 16,
                        rel_emb + (long)sRid[kc + cand] * DK + off * 4); }
        { const int cand = tid >> 5, off = tid & 31;                     // ent
          CP_ASYNC_CG16(dst + (1024 + tid) * 16,
                        ent_emb + (long)sEid[kc + cand] * DK + off * 4); }
        { const int cand = tid >> 5, off = tid & 31;                     // V slice
          CP_ASYNC_CG16(smem_u32(sV + (kc + cand) * DV + off * 4),
                        V_kb + base_k + (long)(kc + cand) * DV + off * 4); }
        CP_ASYNC_COMMIT();
    };

    issue_chunk(0, 0);      // DRAM streaming starts before the Qw wait
    issue_chunk(1, 1);

    // qb = Q . b_ctx (overlaps in-flight copies + producer wait)
    const float4 qv  = ((const float4*)sQ)[lane];
    const float4 bv  = ((const float4*)b_ctx)[lane];
    float qb = qv.x * bv.x + qv.y * bv.y + qv.z * bv.z + qv.w * bv.w;
#pragma unroll
    for (int off = 16; off; off >>= 1) qb += __shfl_xor_sync(~0u, qb, off);

    // ---- wait for this row's Qw producer ----
    const int grp = row >> 5;   // QW_ROWS == 32
    if (tid == 0) {
        while (atomicAdd(&g_flag[grp], 0u) == 0u) __nanosleep(100);
        __threadfence();
        // consumer bookkeeping: 32nd consumer resets state for next replay
        const unsigned prev = atomicAdd(&g_cnt[grp], 1u);
        if (prev == 31u) { g_cnt[grp] = 0u; atomicExch(&g_flag[grp], 0u); }
    }
    __syncthreads();

    sQW[tid] = g_qw[(long)row * DCTX + tid];
    __syncthreads();

    const float qmn = q_min[row];
    const float qmx = q_max[row];
    const float inv_sqrt = 0.08838834764831843f; // 1/sqrt(128)
    const float4 qwa = ((const float4*)sQW)[lane];
    const float4 qwb = ((const float4*)sQW)[lane + 32];

#pragma unroll
    for (int c = 0; c < NCHUNK; ++c) {
        if (c < NCHUNK - 1) { CP_ASYNC_WAIT(1); } else { CP_ASYNC_WAIT(0); }
        __syncthreads();    // chunk c data visible to all threads

        const float* S = sA + (c & 1) * STAGE_F;
        const int k = c * CHUNK + warp;   // this warp's candidate

        const float4 kv = ((const float4*)S)[warp * 32 + lane];
        const float4 c0 = ((const float4*)(S + 1024))[warp * 64 + lane];
        const float4 c1 = ((const float4*)(S + 1024))[warp * 64 + lane + 32];
        const float4 rv = ((const float4*)(S + 3072))[warp * 32 + lane];
        const float4 ev = ((const float4*)(S + 4096))[warp * 32 + lane];

        float sem = qv.x * kv.x + qv.y * kv.y + qv.z * kv.z + qv.w * kv.w;
        float cx  = qv.x * (rv.x + ev.x) + qv.y * (rv.y + ev.y)
                  + qv.z * (rv.z + ev.z) + qv.w * (rv.w + ev.w);
        cx += qwa.x * c0.x + qwa.y * c0.y + qwa.z * c0.z + qwa.w * c0.w;
        cx += qwb.x * c1.x + qwb.y * c1.y + qwb.z * c1.z + qwb.w * c1.w;

        float tot = sem + GAMMA * cx;
#pragma unroll
        for (int off = 16; off; off >>= 1) tot += __shfl_xor_sync(~0u, tot, off);

        if (lane == 0) {
            const float tmin = sTmin[k];
            const float tmax = sTmax[k];
            const float inter = fmaxf(fminf(qmx, tmax) - fmaxf(qmn, tmin), 0.f);
            const float uni   = fmaxf(qmx, tmax) - fminf(qmn, tmin);
            const float ts    = inter / (uni + 1e-6f);
            sS[k] = (tot + GAMMA * qb) * inv_sqrt + ETA * ts;
        }
        __syncthreads();    // compute done before buffer reuse
        if (c + 2 < NCHUNK) issue_chunk(c + 2, c & 1);
    }

    // Softmax over 64 scores (warp 0)
    if (warp == 0) {
        float s0 = sS[lane], s1 = sS[lane + 32];
        float m = fmaxf(s0, s1);
#pragma unroll
        for (int off = 16; off; off >>= 1) m = fmaxf(m, __shfl_xor_sync(~0u, m, off));
        float e0 = __expf((s0 - m) * INV_TEMP);
        float e1 = __expf((s1 - m) * INV_TEMP);
        float sum = e0 + e1;
#pragma unroll
        for (int off = 16; off; off >>= 1) sum += __shfl_xor_sync(~0u, sum, off);
        const float inv = 1.0f / sum;
        const float a0 = e0 * inv, a1 = e1 * inv;
        sS[lane]      = a0;
        sS[lane + 32] = a1;
        out_alpha[row * KCAND + lane]      = a0;
        out_alpha[row * KCAND + lane + 32] = a1;
    }
    __syncthreads();

    // V_tilde = sum_k alpha[k] * V[k,:] from smem — split k across 2 groups
    const int g = tid >> 7;
    const int d = tid & 127;
    const float* vs = sV + g * 32 * DV;
    float acc = 0.f;
#pragma unroll
    for (int kk = 0; kk < 32; ++kk)
        acc = fmaf(sS[g * 32 + kk], vs[kk * DV + d], acc);
    float* sVp = sQW;   // reuse (Qw already consumed into registers)
    if (g) sVp[d] = acc;
    __syncthreads();
    if (!g) out_v[(long)row * DV + d] = acc + sVp[d];
}

// ---------------------------------------------------------------------------
extern "C" void kernel_launch(void* const* d_in, const int* in_sizes, int n_in,
                              void* d_out, int out_size) {
    const float* Q     = (const float*)d_in[0];
    const float* K_kb  = (const float*)d_in[1];
    const float* V_kb  = (const float*)d_in[2];
    const float* ctx   = (const float*)d_in[3];
    const float* W     = (const float*)d_in[4];
    const float* b_ctx = (const float*)d_in[5];
    const float* rel   = (const float*)d_in[6];
    const float* ent   = (const float*)d_in[7];
    const float* qmin  = (const float*)d_in[8];
    const float* qmax  = (const float*)d_in[9];
    const float* tmin  = (const float*)d_in[10];
    const float* tmax  = (const float*)d_in[11];
    const int*   rid   = (const int*)d_in[12];
    const int*   eid   = (const int*)d_in[13];

    float* out       = (float*)d_out;
    float* out_alpha = out;                    // [BT, 64]
    float* out_v     = out + BT * KCAND;       // [BT, 128]

    cudaFuncSetAttribute(kb_kernel,
                         cudaFuncAttributeMaxDynamicSharedMemorySize,
                         SMEM_BYTES);

    kb_kernel<<<QW_BLOCKS + BT, 256, SMEM_BYTES>>>(
        Q, K_kb, V_kb, ctx, W, b_ctx, rel, ent,
        qmin, qmax, tmin, tmax, rid, eid, out_alpha, out_v);
}

// round 8
// speedup vs baseline: 1.1972x; 1.1972x over previous
#include <cuda_runtime.h>

#define BT     4096      // B*T
#define KCAND  64
#define DK     128
#define DCTX   256
#define DV     128
#define GAMMA  1.0f
#define ETA    1.0f
#define INV_TEMP 1.0f

#define CHUNK   8        // candidates per pipeline stage
#define NCHUNK  8        // KCAND / CHUNK
#define STAGE_F 5120     // floats per stage: K 1024 + ctx 2048 + rel 1024 + ent 1024
#define SMEM_FLOATS (2*STAGE_F + KCAND*DV + DK + DCTX + KCAND + 4*KCAND)
#define SMEM_BYTES  (SMEM_FLOATS * 4)   // 76544 B

#define QW_ROWS   32     // rows per qw block -> grid 128

// 4 MB scratch for Qw = Q @ W_ctx (device global => allowed, no allocation)
__device__ float g_qw[BT * DCTX];

#define CP_ASYNC_CG16(dst, src) \
    asm volatile("cp.async.cg.shared.global [%0], [%1], 16;\n" :: "r"(dst), "l"(src))
#define CP_ASYNC_COMMIT() asm volatile("cp.async.commit_group;\n" ::)
#define CP_ASYNC_WAIT(N)  asm volatile("cp.async.wait_group %0;\n" :: "n"(N))

__device__ __forceinline__ unsigned smem_u32(const void* p) {
    return (unsigned)__cvta_generic_to_shared(p);
}

// ---------------------------------------------------------------------------
// Kernel 1: Qw[32 rows/block] = Q @ W_ctx.  Register-tiled 4 rows x 8 cols per
// thread: 32 FMA per (1 LDS.128 + 2 LDG.128) => FMA-bound, ~4-5us full grid.
// ---------------------------------------------------------------------------
__global__ __launch_bounds__(256) void qw_kernel(const float* __restrict__ Q,
                                                 const float* __restrict__ W_ctx) {
    __shared__ float qsh[DK * 36];     // transposed Q tile: [128][36] padded
    const int tid = threadIdx.x;
    const int rowbase = blockIdx.x * QW_ROWS;

#pragma unroll
    for (int i = 0; i < 16; ++i) {
        const int idx = tid + i * 256;      // 0..4095
        const int r = idx >> 7;             // 0..31
        const int d = idx & 127;
        qsh[d * 36 + r] = Q[(long)(rowbase + r) * DK + d];
    }
    __syncthreads();

    const int rg = tid >> 5;                // row group: rows rg*4..+3
    const int cq = (tid & 31) * 2;          // float4 col idx: cols cq*4..cq*4+7
    const float4* W4 = (const float4*)W_ctx;

    float4 a00 = make_float4(0.f,0.f,0.f,0.f), a01 = a00;
    float4 a10 = a00, a11 = a00, a20 = a00, a21 = a00, a30 = a00, a31 = a00;

#pragma unroll 2
    for (int d = 0; d < DK; ++d) {
        const float4 q4 = *(const float4*)(qsh + d * 36 + rg * 4);  // broadcast
        const float4 w0 = W4[d * 64 + cq];
        const float4 w1 = W4[d * 64 + cq + 1];
        a00.x = fmaf(q4.x, w0.x, a00.x); a00.y = fmaf(q4.x, w0.y, a00.y);
        a00.z = fmaf(q4.x, w0.z, a00.z); a00.w = fmaf(q4.x, w0.w, a00.w);
        a01.x = fmaf(q4.x, w1.x, a01.x); a01.y = fmaf(q4.x, w1.y, a01.y);
        a01.z = fmaf(q4.x, w1.z, a01.z); a01.w = fmaf(q4.x, w1.w, a01.w);
        a10.x = fmaf(q4.y, w0.x, a10.x); a10.y = fmaf(q4.y, w0.y, a10.y);
        a10.z = fmaf(q4.y, w0.z, a10.z); a10.w = fmaf(q4.y, w0.w, a10.w);
        a11.x = fmaf(q4.y, w1.x, a11.x); a11.y = fmaf(q4.y, w1.y, a11.y);
        a11.z = fmaf(q4.y, w1.z, a11.z); a11.w = fmaf(q4.y, w1.w, a11.w);
        a20.x = fmaf(q4.z, w0.x, a20.x); a20.y = fmaf(q4.z, w0.y, a20.y);
        a20.z = fmaf(q4.z, w0.z, a20.z); a20.w = fmaf(q4.z, w0.w, a20.w);
        a21.x = fmaf(q4.z, w1.x, a21.x); a21.y = fmaf(q4.z, w1.y, a21.y);
        a21.z = fmaf(q4.z, w1.z, a21.z); a21.w = fmaf(q4.z, w1.w, a21.w);
        a30.x = fmaf(q4.w, w0.x, a30.x); a30.y = fmaf(q4.w, w0.y, a30.y);
        a30.z = fmaf(q4.w, w0.z, a30.z); a30.w = fmaf(q4.w, w0.w, a30.w);
        a31.x = fmaf(q4.w, w1.x, a31.x); a31.y = fmaf(q4.w, w1.y, a31.y);
        a31.z = fmaf(q4.w, w1.z, a31.z); a31.w = fmaf(q4.w, w1.w, a31.w);
    }

    float4* o0 = (float4*)(g_qw + (long)(rowbase + rg * 4 + 0) * DCTX);
    float4* o1 = (float4*)(g_qw + (long)(rowbase + rg * 4 + 1) * DCTX);
    float4* o2 = (float4*)(g_qw + (long)(rowbase + rg * 4 + 2) * DCTX);
    float4* o3 = (float4*)(g_qw + (long)(rowbase + rg * 4 + 3) * DCTX);
    o0[cq] = a00; o0[cq + 1] = a01;
    o1[cq] = a10; o1[cq + 1] = a11;
    o2[cq] = a20; o2[cq + 1] = a21;
    o3[cq] = a30; o3[cq + 1] = a31;
}

// ---------------------------------------------------------------------------
// Kernel 2: one block per (b,t) row. Double-buffered cp.async streaming of
// K/ctx/rel/ent + V; smem-only compute. (Identical to the 104.4us R4 path.)
// ---------------------------------------------------------------------------
__global__ __launch_bounds__(256) void kb_main_kernel(
    const float* __restrict__ Q,
    const float* __restrict__ K_kb,
    const float* __restrict__ V_kb,
    const float* __restrict__ ctx,
    const float* __restrict__ b_ctx,
    const float* __restrict__ rel_emb,
    const float* __restrict__ ent_emb,
    const float* __restrict__ q_min,
    const float* __restrict__ q_max,
    const float* __restrict__ tau_min,
    const float* __restrict__ tau_max,
    const int*   __restrict__ rel_id,
    const int*   __restrict__ ent_id,
    float* __restrict__ out_alpha,
    float* __restrict__ out_v)
{
    extern __shared__ float smem[];
    float* sA    = smem;                         // [2][STAGE_F] stages
    float* sV    = smem + 2 * STAGE_F;           // [64][128]
    float* sQ    = sV + KCAND * DV;              // 128
    float* sQW   = sQ + DK;                      // 256
    float* sS    = sQW + DCTX;                   // 64 scores -> alpha
    int*   sRid  = (int*)(sS + KCAND);           // 64
    int*   sEid  = sRid + KCAND;                 // 64
    float* sTmin = (float*)(sEid + KCAND);       // 64
    float* sTmax = sTmin + KCAND;                // 64

    const int row  = blockIdx.x;
    const int tid  = threadIdx.x;
    const int warp = tid >> 5;
    const int lane = tid & 31;

    const long base_k = (long)row * KCAND * DK;
    const long base_c = (long)row * KCAND * DCTX;

    // ---- prologue: small per-row data ----
    if (tid < 64)        sRid [tid]       = rel_id [row * KCAND + tid];
    else if (tid < 128)  sEid [tid - 64]  = ent_id [row * KCAND + tid - 64];
    else if (tid < 192)  sTmin[tid - 128] = tau_min[row * KCAND + tid - 128];
    else                 sTmax[tid - 192] = tau_max[row * KCAND + tid - 192];
    if (tid < DK) sQ[tid] = Q[(long)row * DK + tid];
    __syncthreads();    // ids (cp.async addresses) + sQ visible

    // ---- chunk issuer: K+ctx+rel+ent stage (20KB) + V slice (4KB), 1 group
    auto issue_chunk = [&](int c, int stg) {
        const int kc = c * CHUNK;
        const unsigned dst = smem_u32(sA + stg * STAGE_F);
        { const int cand = tid >> 5, off = tid & 31;                     // K
          CP_ASYNC_CG16(dst + tid * 16,
                        K_kb + base_k + (long)(kc + cand) * DK + off * 4); }
        { const int cand = tid >> 6, off = tid & 63;                     // ctx lo
          CP_ASYNC_CG16(dst + (256 + tid) * 16,
                        ctx + base_c + (long)(kc + cand) * DCTX + off * 4); }
        { const int t = tid + 256; const int cand = t >> 6, off = t & 63; // ctx hi
          CP_ASYNC_CG16(dst + (256 + t) * 16,
                        ctx + base_c + (long)(kc + cand) * DCTX + off * 4); }
        { const int cand = tid >> 5, off = tid & 31;                     // rel
          CP_ASYNC_CG16(dst + (768 + tid) * 16,
                        rel_emb + (long)sRid[kc + cand] * DK + off * 4); }
        { const int cand = tid >> 5, off = tid & 31;                     // ent
          CP_ASYNC_CG16(dst + (1024 + tid) * 16,
                        ent_emb + (long)sEid[kc + cand] * DK + off * 4); }
        { const int cand = tid >> 5, off = tid & 31;                     // V slice
          CP_ASYNC_CG16(smem_u32(sV + (kc + cand) * DV + off * 4),
                        V_kb + base_k + (long)(kc + cand) * DV + off * 4); }
        CP_ASYNC_COMMIT();
    };

    issue_chunk(0, 0);
    issue_chunk(1, 1);

    // qb = Q . b_ctx (overlaps in-flight copies)
    const float4 qv  = ((const float4*)sQ)[lane];
    const float4 bv  = ((const float4*)b_ctx)[lane];
    float qb = qv.x * bv.x + qv.y * bv.y + qv.z * bv.z + qv.w * bv.w;
#pragma unroll
    for (int off = 16; off; off >>= 1) qb += __shfl_xor_sync(~0u, qb, off);

    sQW[tid] = g_qw[(long)row * DCTX + tid];
    __syncthreads();

    const float qmn = q_min[row];
    const float qmx = q_max[row];
    const float inv_sqrt = 0.08838834764831843f; // 1/sqrt(128)
    const float4 qwa = ((const float4*)sQW)[lane];
    const float4 qwb = ((const float4*)sQW)[lane + 32];

#pragma unroll
    for (int c = 0; c < NCHUNK; ++c) {
        if (c < NCHUNK - 1) { CP_ASYNC_WAIT(1); } else { CP_ASYNC_WAIT(0); }
        __syncthreads();    // chunk c data visible to all threads

        const float* S = sA + (c & 1) * STAGE_F;
        const int k = c * CHUNK + warp;   // this warp's candidate

        const float4 kv = ((const float4*)S)[warp * 32 + lane];
        const float4 c0 = ((const float4*)(S + 1024))[warp * 64 + lane];
        const float4 c1 = ((const float4*)(S + 1024))[warp * 64 + lane + 32];
        const float4 rv = ((const float4*)(S + 3072))[warp * 32 + lane];
        const float4 ev = ((const float4*)(S + 4096))[warp * 32 + lane];

        float sem = qv.x * kv.x + qv.y * kv.y + qv.z * kv.z + qv.w * kv.w;
        float cx  = qv.x * (rv.x + ev.x) + qv.y * (rv.y + ev.y)
                  + qv.z * (rv.z + ev.z) + qv.w * (rv.w + ev.w);
        cx += qwa.x * c0.x + qwa.y * c0.y + qwa.z * c0.z + qwa.w * c0.w;
        cx += qwb.x * c1.x + qwb.y * c1.y + qwb.z * c1.z + qwb.w * c1.w;

        float tot = sem + GAMMA * cx;
#pragma unroll
        for (int off = 16; off; off >>= 1) tot += __shfl_xor_sync(~0u, tot, off);

        if (lane == 0) {
            const float tmin = sTmin[k];
            const float tmax = sTmax[k];
            const float inter = fmaxf(fminf(qmx, tmax) - fmaxf(qmn, tmin), 0.f);
            const float uni   = fmaxf(qmx, tmax) - fminf(qmn, tmin);
            const float ts    = inter / (uni + 1e-6f);
            sS[k] = (tot + GAMMA * qb) * inv_sqrt + ETA * ts;
        }
        __syncthreads();    // compute done before buffer reuse
        if (c + 2 < NCHUNK) issue_chunk(c + 2, c & 1);
    }

    // Softmax over 64 scores (warp 0)
    if (warp == 0) {
        float s0 = sS[lane], s1 = sS[lane + 32];
        float m = fmaxf(s0, s1);
#pragma unroll
        for (int off = 16; off; off >>= 1) m = fmaxf(m, __shfl_xor_sync(~0u, m, off));
        float e0 = __expf((s0 - m) * INV_TEMP);
        float e1 = __expf((s1 - m) * INV_TEMP);
        float sum = e0 + e1;
#pragma unroll
        for (int off = 16; off; off >>= 1) sum += __shfl_xor_sync(~0u, sum, off);
        const float inv = 1.0f / sum;
        const float a0 = e0 * inv, a1 = e1 * inv;
        sS[lane]      = a0;
        sS[lane + 32] = a1;
        out_alpha[row * KCAND + lane]      = a0;
        out_alpha[row * KCAND + lane + 32] = a1;
    }
    __syncthreads();

    // V_tilde = sum_k alpha[k] * V[k,:] from smem — split k across 2 groups
    const int g = tid >> 7;
    const int d = tid & 127;
    const float* vs = sV + g * 32 * DV;
    float acc = 0.f;
#pragma unroll
    for (int kk = 0; kk < 32; ++kk)
        acc = fmaf(sS[g * 32 + kk], vs[kk * DV + d], acc);
    float* sVp = sQW;   // reuse (Qw already consumed into registers)
    if (g) sVp[d] = acc;
    __syncthreads();
    if (!g) out_v[(long)row * DV + d] = acc + sVp[d];
}

// ---------------------------------------------------------------------------
extern "C" void kernel_launch(void* const* d_in, const int* in_sizes, int n_in,
                              void* d_out, int out_size) {
    const float* Q     = (const float*)d_in[0];
    const float* K_kb  = (const float*)d_in[1];
    const float* V_kb  = (const float*)d_in[2];
    const float* ctx   = (const float*)d_in[3];
    const float* W     = (const float*)d_in[4];
    const float* b_ctx = (const float*)d_in[5];
    const float* rel   = (const float*)d_in[6];
    const float* ent   = (const float*)d_in[7];
    const float* qmin  = (const float*)d_in[8];
    const float* qmax  = (const float*)d_in[9];
    const float* tmin  = (const float*)d_in[10];
    const float* tmax  = (const float*)d_in[11];
    const int*   rid   = (const int*)d_in[12];
    const int*   eid   = (const int*)d_in[13];

    float* out       = (float*)d_out;
    float* out_alpha = out;                    // [BT, 64]
    float* out_v     = out + BT * KCAND;       // [BT, 128]

    cudaFuncSetAttribute(kb_main_kernel,
                         cudaFuncAttributeMaxDynamicSharedMemorySize,
                         SMEM_BYTES);

    qw_kernel<<<BT / QW_ROWS, 256>>>(Q, W);
    kb_main_kernel<<<BT, 256, SMEM_BYTES>>>(Q, K_kb, V_kb, ctx, b_ctx, rel, ent,
                                            qmin, qmax, tmin, tmax, rid, eid,
                                            out_alpha, out_v);
}

// round 9
// speedup vs baseline: 1.2450x; 1.0399x over previous
#include <cuda_runtime.h>

#define BT     4096      // B*T
#define KCAND  64
#define DK     128
#define DCTX   256
#define DV     128
#define GAMMA  1.0f
#define ETA    1.0f
#define INV_TEMP 1.0f

#define CHUNK   8        // candidates per pipeline stage
#define NCHUNK  8        // KCAND / CHUNK
#define STAGE_F 5120     // floats per stage: K 1024 + ctx 2048 + rel 1024 + ent 1024
#define SMEM_FLOATS (2*STAGE_F + KCAND*DV + DK + DCTX + KCAND + 4*KCAND)
#define SMEM_BYTES  (SMEM_FLOATS * 4)   // 76544 B -> 3 blocks/SM

#define NBLK   888       // 2 waves @3 blocks/SM (444) or 3 waves @2 (296)
#define NRMAX  5         // max rows per block (4096/888 -> 4 or 5)

// 4 MB scratch for Qw rows; each block writes ONLY the rows it later reads
// (same-CTA produce/consume, no cross-block synchronization needed).
__device__ float g_qw[BT * DCTX];

#define CP_ASYNC_CG16(dst, src) \
    asm volatile("cp.async.cg.shared.global [%0], [%1], 16;\n" :: "r"(dst), "l"(src))
#define CP_ASYNC_COMMIT() asm volatile("cp.async.commit_group;\n" ::)
#define CP_ASYNC_WAIT(N)  asm volatile("cp.async.wait_group %0;\n" :: "n"(N))

__device__ __forceinline__ unsigned smem_u32(const void* p) {
    return (unsigned)__cvta_generic_to_shared(p);
}

// ---------------------------------------------------------------------------
// Single kernel, grid NBLK: block b owns rows [b*BT/NBLK, (b+1)*BT/NBLK).
// Prologue computes the block's own Qw rows (overlapped with chunk0 cp.async),
// then the proven double-buffered streaming pipeline runs per row.
// ---------------------------------------------------------------------------
__global__ __launch_bounds__(256) void kb_kernel(
    const float* __restrict__ Q,
    const float* __restrict__ K_kb,
    const float* __restrict__ V_kb,
    const float* __restrict__ ctx,
    const float* __restrict__ W_ctx,
    const float* __restrict__ b_ctx,
    const float* __restrict__ rel_emb,
    const float* __restrict__ ent_emb,
    const float* __restrict__ q_min,
    const float* __restrict__ q_max,
    const float* __restrict__ tau_min,
    const float* __restrict__ tau_max,
    const int*   __restrict__ rel_id,
    const int*   __restrict__ ent_id,
    float* __restrict__ out_alpha,
    float* __restrict__ out_v)
{
    extern __shared__ float smem[];
    float* sA    = smem;                         // [2][STAGE_F] stages
    float* sV    = smem + 2 * STAGE_F;           // [64][128]
    float* sQ    = sV + KCAND * DV;              // 128
    float* sQW   = sQ + DK;                      // 256
    float* sS    = sQW + DCTX;                   // 64 scores -> alpha
    int*   sRid  = (int*)(sS + KCAND);           // 64
    int*   sEid  = sRid + KCAND;                 // 64
    float* sTmin = (float*)(sEid + KCAND);       // 64
    float* sTmax = sTmin + KCAND;                // 64

    const int tid  = threadIdx.x;
    const int warp = tid >> 5;
    const int lane = tid & 31;

    const int b  = blockIdx.x;
    const int r0 = (b * BT) / NBLK;
    const int r1 = ((b + 1) * BT) / NBLK;
    const int nr = r1 - r0;

    long base_k = 0, base_c = 0;   // current row bases (captured by lambdas)

    auto load_row_small = [&](int row) {
        if (tid < 64)        sRid [tid]       = rel_id [row * KCAND + tid];
        else if (tid < 128)  sEid [tid - 64]  = ent_id [row * KCAND + tid - 64];
        else if (tid < 192)  sTmin[tid - 128] = tau_min[row * KCAND + tid - 128];
        else                 sTmax[tid - 192] = tau_max[row * KCAND + tid - 192];
        if (tid < DK) sQ[tid] = Q[(long)row * DK + tid];
    };

    // chunk issuer: K+ctx+rel+ent stage (20KB) + V slice (4KB), one group
    auto issue_chunk = [&](int c, int stg) {
        const int kc = c * CHUNK;
        const unsigned dst = smem_u32(sA + stg * STAGE_F);
        { const int cand = tid >> 5, off = tid & 31;                     // K
          CP_ASYNC_CG16(dst + tid * 16,
                        K_kb + base_k + (long)(kc + cand) * DK + off * 4); }
        { const int cand = tid >> 6, off = tid & 63;                     // ctx lo
          CP_ASYNC_CG16(dst + (256 + tid) * 16,
                        ctx + base_c + (long)(kc + cand) * DCTX + off * 4); }
        { const int t = tid + 256; const int cand = t >> 6, off = t & 63; // ctx hi
          CP_ASYNC_CG16(dst + (256 + t) * 16,
                        ctx + base_c + (long)(kc + cand) * DCTX + off * 4); }
        { const int cand = tid >> 5, off = tid & 31;                     // rel
          CP_ASYNC_CG16(dst + (768 + tid) * 16,
                        rel_emb + (long)sRid[kc + cand] * DK + off * 4); }
        { const int cand = tid >> 5, off = tid & 31;                     // ent
          CP_ASYNC_CG16(dst + (1024 + tid) * 16,
                        ent_emb + (long)sEid[kc + cand] * DK + off * 4); }
        { const int cand = tid >> 5, off = tid & 31;                     // V slice
          CP_ASYNC_CG16(smem_u32(sV + (kc + cand) * DV + off * 4),
                        V_kb + base_k + (long)(kc + cand) * DV + off * 4); }
        CP_ASYNC_COMMIT();
    };

    // ---- first row's small data, then start DRAM streaming immediately ----
    load_row_small(r0);
    __syncthreads();
    base_k = (long)r0 * KCAND * DK;
    base_c = (long)r0 * KCAND * DCTX;
    issue_chunk(0, 0);

    // ---- Qw prologue: this block's nr rows, overlapped with chunk0 copies.
    // Q scratch aliases stage 1 (released before chunk1 is issued).
    {
        float* qs = sA + STAGE_F;              // [NRMAX][DK]
        for (int i = tid; i < NRMAX * DK; i += 256) {
            int r = i >> 7; if (r >= nr) r = 0;    // pad with row 0 (unused)
            qs[i] = Q[(long)(r0 + r) * DK + (i & 127)];
        }
        __syncthreads();

        const int c = tid;                     // output column 0..255
        float acc[NRMAX];
#pragma unroll
        for (int r = 0; r < NRMAX; ++r) acc[r] = 0.f;
#pragma unroll 4
        for (int d = 0; d < DK; ++d) {
            const float w = W_ctx[d * DCTX + c];   // coalesced, L2-hot
#pragma unroll
            for (int r = 0; r < NRMAX; ++r)
                acc[r] = fmaf(qs[r * DK + d], w, acc[r]);
        }
        for (int r = 0; r < nr; ++r)
            g_qw[(long)(r0 + r) * DCTX + c] = acc[r];
        __syncthreads();   // qs reads complete before chunk1 reuses stage 1
    }
    issue_chunk(1, 1);

    const float inv_sqrt = 0.08838834764831843f;   // 1/sqrt(128)

    // =========================== row loop ===============================
    for (int row = r0; row < r1; ++row) {
        if (row > r0) {
            load_row_small(row);
            __syncthreads();          // small data + sQ visible; epilogue done
            base_k = (long)row * KCAND * DK;
            base_c = (long)row * KCAND * DCTX;
            issue_chunk(0, 0);
            issue_chunk(1, 1);
        }

        // qb = Q . b_ctx (overlaps in-flight copies)
        const float4 qv = ((const float4*)sQ)[lane];
        const float4 bv = ((const float4*)b_ctx)[lane];
        float qb = qv.x * bv.x + qv.y * bv.y + qv.z * bv.z + qv.w * bv.w;
#pragma unroll
        for (int off = 16; off; off >>= 1) qb += __shfl_xor_sync(~0u, qb, off);

        // this row's Qw (self-produced, same-CTA visible)
        sQW[tid] = g_qw[(long)row * DCTX + tid];
        __syncthreads();

        const float qmn = q_min[row];
        const float qmx = q_max[row];
        const float4 qwa = ((const float4*)sQW)[lane];
        const float4 qwb = ((const float4*)sQW)[lane + 32];

#pragma unroll
        for (int c = 0; c < NCHUNK; ++c) {
            if (c < NCHUNK - 1) { CP_ASYNC_WAIT(1); } else { CP_ASYNC_WAIT(0); }
            __syncthreads();    // chunk c data visible to all threads

            const float* S = sA + (c & 1) * STAGE_F;
            const int k = c * CHUNK + warp;   // this warp's candidate

            const float4 kv = ((const float4*)S)[warp * 32 + lane];
            const float4 c0 = ((const float4*)(S + 1024))[warp * 64 + lane];
            const float4 c1 = ((const float4*)(S + 1024))[warp * 64 + lane + 32];
            const float4 rv = ((const float4*)(S + 3072))[warp * 32 + lane];
            const float4 ev = ((const float4*)(S + 4096))[warp * 32 + lane];

            float sem = qv.x * kv.x + qv.y * kv.y + qv.z * kv.z + qv.w * kv.w;
            float cx  = qv.x * (rv.x + ev.x) + qv.y * (rv.y + ev.y)
                      + qv.z * (rv.z + ev.z) + qv.w * (rv.w + ev.w);
            cx += qwa.x * c0.x + qwa.y * c0.y + qwa.z * c0.z + qwa.w * c0.w;
            cx += qwb.x * c1.x + qwb.y * c1.y + qwb.z * c1.z + qwb.w * c1.w;

            float tot = sem + GAMMA * cx;
#pragma unroll
            for (int off = 16; off; off >>= 1)
                tot += __shfl_xor_sync(~0u, tot, off);

            if (lane == 0) {
                const float tmin = sTmin[k];
                const float tmax = sTmax[k];
                const float inter = fmaxf(fminf(qmx, tmax) - fmaxf(qmn, tmin), 0.f);
                const float uni   = fmaxf(qmx, tmax) - fminf(qmn, tmin);
                const float ts    = inter / (uni + 1e-6f);
                sS[k] = (tot + GAMMA * qb) * inv_sqrt + ETA * ts;
            }
            __syncthreads();    // compute done before buffer reuse
            if (c + 2 < NCHUNK) issue_chunk(c + 2, c & 1);
        }

        // Softmax over 64 scores (warp 0)
        if (warp == 0) {
            float s0 = sS[lane], s1 = sS[lane + 32];
            float m = fmaxf(s0, s1);
#pragma unroll
            for (int off = 16; off; off >>= 1)
                m = fmaxf(m, __shfl_xor_sync(~0u, m, off));
            float e0 = __expf((s0 - m) * INV_TEMP);
            float e1 = __expf((s1 - m) * INV_TEMP);
            float sum = e0 + e1;
#pragma unroll
            for (int off = 16; off; off >>= 1)
                sum += __shfl_xor_sync(~0u, sum, off);
            const float inv = 1.0f / sum;
            const float a0 = e0 * inv, a1 = e1 * inv;
            sS[lane]      = a0;
            sS[lane + 32] = a1;
            out_alpha[row * KCAND + lane]      = a0;
            out_alpha[row * KCAND + lane + 32] = a1;
        }
        __syncthreads();

        // V_tilde = sum_k alpha[k] * V[k,:] from smem — k split across 2 groups
        const int g = tid >> 7;
        const int d = tid & 127;
        const float* vs = sV + g * 32 * DV;
        float acc = 0.f;
#pragma unroll
        for (int kk = 0; kk < 32; ++kk)
            acc = fmaf(sS[g * 32 + kk], vs[kk * DV + d], acc);
        float* sVp = sQW;   // reuse (Qw already consumed into registers)
        if (g) sVp[d] = acc;
        __syncthreads();
        if (!g) out_v[(long)row * DV + d] = acc + sVp[d];
        // next iteration's load_row_small + barrier protects sVp reads
    }
}

// ---------------------------------------------------------------------------
extern "C" void kernel_launch(void* const* d_in, const int* in_sizes, int n_in,
                              void* d_out, int out_size) {
    const float* Q     = (const float*)d_in[0];
    const float* K_kb  = (const float*)d_in[1];
    const float* V_kb  = (const float*)d_in[2];
    const float* ctx   = (const float*)d_in[3];
    const float* W     = (const float*)d_in[4];
    const float* b_ctx = (const float*)d_in[5];
    const float* rel   = (const float*)d_in[6];
    const float* ent   = (const float*)d_in[7];
    const float* qmin  = (const float*)d_in[8];
    const float* qmax  = (const float*)d_in[9];
    const float* tmin  = (const float*)d_in[10];
    const float* tmax  = (const float*)d_in[11];
    const int*   rid   = (const int*)d_in[12];
    const int*   eid   = (const int*)d_in[13];

    float* out       = (float*)d_out;
    float* out_alpha = out;                    // [BT, 64]
    float* out_v     = out + BT * KCAND;       // [BT, 128]

    cudaFuncSetAttribute(kb_kernel,
                         cudaFuncAttributeMaxDynamicSharedMemorySize,
                         SMEM_BYTES);

    kb_kernel<<<NBLK, 256, SMEM_BYTES>>>(Q, K_kb, V_kb, ctx, W, b_ctx,
                                         rel, ent, qmin, qmax, tmin, tmax,
                                         rid, eid, out_alpha, out_v);
}

// round 10
// speedup vs baseline: 1.2504x; 1.0044x over previous
#include <cuda_runtime.h>

#define BT     4096      // B*T
#define KCAND  64
#define DK     128
#define DCTX   256
#define DV     128
#define GAMMA  1.0f
#define ETA    1.0f
#define INV_TEMP 1.0f

#define CHUNK   8        // candidates per pipeline stage
#define NCHUNK  8        // KCAND / CHUNK
#define STAGE_F 5120     // floats per stage: K 1024 + ctx 2048 + rel 1024 + ent 1024
#define SMEM_FLOATS (2*STAGE_F + KCAND*DV + DK + DCTX + KCAND + 4*KCAND)
#define SMEM_BYTES  (SMEM_FLOATS * 4)   // 76544 B -> 3 blocks/SM

#define QW_ROWS 8        // rows per qw block -> grid 512

// 4 MB scratch for Qw = Q @ W_ctx (device global => allowed, no allocation)
__device__ float g_qw[BT * DCTX];

#define CP_ASYNC_CG16(dst, src) \
    asm volatile("cp.async.cg.shared.global [%0], [%1], 16;\n" :: "r"(dst), "l"(src))
#define CP_ASYNC_COMMIT() asm volatile("cp.async.commit_group;\n" ::)
#define CP_ASYNC_WAIT(N)  asm volatile("cp.async.wait_group %0;\n" :: "n"(N))

__device__ __forceinline__ unsigned smem_u32(const void* p) {
    return (unsigned)__cvta_generic_to_shared(p);
}

// ---------------------------------------------------------------------------
// Kernel 1 (PDL primary): Qw[8 rows/block] = Q @ W_ctx, grid 512.
// Thread = 2 rows x 4 cols: per d, 2 broadcast LDS + 1 LDG.128 per 8 FFMA.
// FFMA-floor-bound: ~8-9us full grid. Small footprint (4KB smem, 8 warps) so
// it co-resides with main-kernel blocks during PDL overlap.
// ---------------------------------------------------------------------------
__global__ __launch_bounds__(256) void qw_kernel(const float* __restrict__ Q,
                                                 const float* __restrict__ W_ctx) {
    __shared__ float qsh[QW_ROWS][DK];    // 4 KB
    const int tid = threadIdx.x;
    const int rowbase = blockIdx.x * QW_ROWS;

#pragma unroll
    for (int i = 0; i < 4; ++i) {
        const int idx = tid + i * 256;    // 0..1023
        qsh[idx >> 7][idx & 127] = Q[(long)rowbase * DK + idx];
    }
    __syncthreads();

    const int r0 = (tid >> 6) * 2;        // row pair: r0, r0+1
    const int r1 = r0 + 1;
    const int cg = tid & 63;              // float4 col group
    const float4* W4 = (const float4*)W_ctx;   // [128][64] float4, L2-hot

    float4 a0 = make_float4(0.f, 0.f, 0.f, 0.f);
    float4 a1 = a0;

#pragma unroll 4
    for (int d = 0; d < DK; ++d) {
        const float4 wv = W4[d * 64 + cg];     // coalesced
        const float q0 = qsh[r0][d];           // broadcast LDS
        const float q1 = qsh[r1][d];
        a0.x = fmaf(q0, wv.x, a0.x); a0.y = fmaf(q0, wv.y, a0.y);
        a0.z = fmaf(q0, wv.z, a0.z); a0.w = fmaf(q0, wv.w, a0.w);
        a1.x = fmaf(q1, wv.x, a1.x); a1.y = fmaf(q1, wv.y, a1.y);
        a1.z = fmaf(q1, wv.z, a1.z); a1.w = fmaf(q1, wv.w, a1.w);
    }

    float4* o0 = (float4*)(g_qw + (long)(rowbase + r0) * DCTX);
    float4* o1 = (float4*)(g_qw + (long)(rowbase + r1) * DCTX);
    o0[cg] = a0;
    o1[cg] = a1;
}

// ---------------------------------------------------------------------------
// Kernel 2 (PDL secondary): one block per (b,t) row — the proven 102.6us path.
// Starts while qw_kernel runs; cudaGridDependencySynchronize() gates g_qw.
// ---------------------------------------------------------------------------
__global__ __launch_bounds__(256) void kb_main_kernel(
    const float* __restrict__ Q,
    const float* __restrict__ K_kb,
    const float* __restrict__ V_kb,
    const float* __restrict__ ctx,
    const float* __restrict__ b_ctx,
    const float* __restrict__ rel_emb,
    const float* __restrict__ ent_emb,
    const float* __restrict__ q_min,
    const float* __restrict__ q_max,
    const float* __restrict__ tau_min,
    const float* __restrict__ tau_max,
    const int*   __restrict__ rel_id,
    const int*   __restrict__ ent_id,
    float* __restrict__ out_alpha,
    float* __restrict__ out_v)
{
    extern __shared__ float smem[];
    float* sA    = smem;                         // [2][STAGE_F] stages
    float* sV    = smem + 2 * STAGE_F;           // [64][128]
    float* sQ    = sV + KCAND * DV;              // 128
    float* sQW   = sQ + DK;                      // 256
    float* sS    = sQW + DCTX;                   // 64 scores -> alpha
    int*   sRid  = (int*)(sS + KCAND);           // 64
    int*   sEid  = sRid + KCAND;                 // 64
    float* sTmin = (float*)(sEid + KCAND);       // 64
    float* sTmax = sTmin + KCAND;                // 64

    const int row  = blockIdx.x;
    const int tid  = threadIdx.x;
    const int warp = tid >> 5;
    const int lane = tid & 31;

    const long base_k = (long)row * KCAND * DK;
    const long base_c = (long)row * KCAND * DCTX;

    // ---- prologue: small per-row data ----
    if (tid < 64)        sRid [tid]       = rel_id [row * KCAND + tid];
    else if (tid < 128)  sEid [tid - 64]  = ent_id [row * KCAND + tid - 64];
    else if (tid < 192)  sTmin[tid - 128] = tau_min[row * KCAND + tid - 128];
    else                 sTmax[tid - 192] = tau_max[row * KCAND + tid - 192];
    if (tid < DK) sQ[tid] = Q[(long)row * DK + tid];
    __syncthreads();    // ids (cp.async addresses) + sQ visible

    // ---- chunk issuer: K+ctx+rel+ent stage (20KB) + V slice (4KB), 1 group
    auto issue_chunk = [&](int c, int stg) {
        const int kc = c * CHUNK;
        const unsigned dst = smem_u32(sA + stg * STAGE_F);
        { const int cand = tid >> 5, off = tid & 31;                     // K
          CP_ASYNC_CG16(dst + tid * 16,
                        K_kb + base_k + (long)(kc + cand) * DK + off * 4); }
        { const int cand = tid >> 6, off = tid & 63;                     // ctx lo
          CP_ASYNC_CG16(dst + (256 + tid) * 16,
                        ctx + base_c + (long)(kc + cand) * DCTX + off * 4); }
        { const int t = tid + 256; const int cand = t >> 6, off = t & 63; // ctx hi
          CP_ASYNC_CG16(dst + (256 + t) * 16,
                        ctx + base_c + (long)(kc + cand) * DCTX + off * 4); }
        { const int cand = tid >> 5, off = tid & 31;                     // rel
          CP_ASYNC_CG16(dst + (768 + tid) * 16,
                        rel_emb + (long)sRid[kc + cand] * DK + off * 4); }
        { const int cand = tid >> 5, off = tid & 31;                     // ent
          CP_ASYNC_CG16(dst + (1024 + tid) * 16,
                        ent_emb + (long)sEid[kc + cand] * DK + off * 4); }
        { const int cand = tid >> 5, off = tid & 31;                     // V slice
          CP_ASYNC_CG16(smem_u32(sV + (kc + cand) * DV + off * 4),
                        V_kb + base_k + (long)(kc + cand) * DV + off * 4); }
        CP_ASYNC_COMMIT();
    };

    issue_chunk(0, 0);      // DRAM streaming starts before the qw dependency
    issue_chunk(1, 1);

    // qb = Q . b_ctx (overlaps in-flight copies and the primary grid)
    const float4 qv  = ((const float4*)sQ)[lane];
    const float4 bv  = ((const float4*)b_ctx)[lane];
    float qb = qv.x * bv.x + qv.y * bv.y + qv.z * bv.z + qv.w * bv.w;
#pragma unroll
    for (int off = 16; off; off >>= 1) qb += __shfl_xor_sync(~0u, qb, off);

    // ---- PDL: wait for qw_kernel grid completion (memory visible after) ----
    cudaGridDependencySynchronize();

    sQW[tid] = g_qw[(long)row * DCTX + tid];
    __syncthreads();

    const float qmn = q_min[row];
    const float qmx = q_max[row];
    const float inv_sqrt = 0.08838834764831843f; // 1/sqrt(128)
    const float4 qwa = ((const float4*)sQW)[lane];
    const float4 qwb = ((const float4*)sQW)[lane + 32];

#pragma unroll
    for (int c = 0; c < NCHUNK; ++c) {
        if (c < NCHUNK - 1) { CP_ASYNC_WAIT(1); } else { CP_ASYNC_WAIT(0); }
        __syncthreads();    // chunk c data visible to all threads

        const float* S = sA + (c & 1) * STAGE_F;
        const int k = c * CHUNK + warp;   // this warp's candidate

        const float4 kv = ((const float4*)S)[warp * 32 + lane];
        const float4 c0 = ((const float4*)(S + 1024))[warp * 64 + lane];
        const float4 c1 = ((const float4*)(S + 1024))[warp * 64 + lane + 32];
        const float4 rv = ((const float4*)(S + 3072))[warp * 32 + lane];
        const float4 ev = ((const float4*)(S + 4096))[warp * 32 + lane];

        float sem = qv.x * kv.x + qv.y * kv.y + qv.z * kv.z + qv.w * kv.w;
        float cx  = qv.x * (rv.x + ev.x) + qv.y * (rv.y + ev.y)
                  + qv.z * (rv.z + ev.z) + qv.w * (rv.w + ev.w);
        cx += qwa.x * c0.x + qwa.y * c0.y + qwa.z * c0.z + qwa.w * c0.w;
        cx += qwb.x * c1.x + qwb.y * c1.y + qwb.z * c1.z + qwb.w * c1.w;

        float tot = sem + GAMMA * cx;
#pragma unroll
        for (int off = 16; off; off >>= 1) tot += __shfl_xor_sync(~0u, tot, off);

        if (lane == 0) {
            const float tmin = sTmin[k];
            const float tmax = sTmax[k];
            const float inter = fmaxf(fminf(qmx, tmax) - fmaxf(qmn, tmin), 0.f);
            const float uni   = fmaxf(qmx, tmax) - fminf(qmn, tmin);
            const float ts    = inter / (uni + 1e-6f);
            sS[k] = (tot + GAMMA * qb) * inv_sqrt + ETA * ts;
        }
        __syncthreads();    // compute done before buffer reuse
        if (c + 2 < NCHUNK) issue_chunk(c + 2, c & 1);
    }

    // Softmax over 64 scores (warp 0)
    if (warp == 0) {
        float s0 = sS[lane], s1 = sS[lane + 32];
        float m = fmaxf(s0, s1);
#pragma unroll
        for (int off = 16; off; off >>= 1) m = fmaxf(m, __shfl_xor_sync(~0u, m, off));
        float e0 = __expf((s0 - m) * INV_TEMP);
        float e1 = __expf((s1 - m) * INV_TEMP);
        float sum = e0 + e1;
#pragma unroll
        for (int off = 16; off; off >>= 1) sum += __shfl_xor_sync(~0u, sum, off);
        const float inv = 1.0f / sum;
        const float a0 = e0 * inv, a1 = e1 * inv;
        sS[lane]      = a0;
        sS[lane + 32] = a1;
        out_alpha[row * KCAND + lane]      = a0;
        out_alpha[row * KCAND + lane + 32] = a1;
    }
    __syncthreads();

    // V_tilde = sum_k alpha[k] * V[k,:] from smem — split k across 2 groups
    const int g = tid >> 7;
    const int d = tid & 127;
    const float* vs = sV + g * 32 * DV;
    float acc = 0.f;
#pragma unroll
    for (int kk = 0; kk < 32; ++kk)
        acc = fmaf(sS[g * 32 + kk], vs[kk * DV + d], acc);
    float* sVp = sQW;   // reuse (Qw already consumed into registers)
    if (g) sVp[d] = acc;
    __syncthreads();
    if (!g) out_v[(long)row * DV + d] = acc + sVp[d];
}

// ---------------------------------------------------------------------------
extern "C" void kernel_launch(void* const* d_in, const int* in_sizes, int n_in,
                              void* d_out, int out_size) {
    const float* Q     = (const float*)d_in[0];
    const float* K_kb  = (const float*)d_in[1];
    const float* V_kb  = (const float*)d_in[2];
    const float* ctx   = (const float*)d_in[3];
    const float* W     = (const float*)d_in[4];
    const float* b_ctx = (const float*)d_in[5];
    const float* rel   = (const float*)d_in[6];
    const float* ent   = (const float*)d_in[7];
    const float* qmin  = (const float*)d_in[8];
    const float* qmax  = (const float*)d_in[9];
    const float* tmin  = (const float*)d_in[10];
    const float* tmax  = (const float*)d_in[11];
    const int*   rid   = (const int*)d_in[12];
    const int*   eid   = (const int*)d_in[13];

    float* out       = (float*)d_out;
    float* out_alpha = out;                    // [BT, 64]
    float* out_v     = out + BT * KCAND;       // [BT, 128]

    cudaFuncSetAttribute(kb_main_kernel,
                         cudaFuncAttributeMaxDynamicSharedMemorySize,
                         SMEM_BYTES);

    // Primary: qw producer (implicit PDL trigger at grid completion)
    qw_kernel<<<BT / QW_ROWS, 256>>>(Q, W);

    // Secondary: programmatic stream serialization — blocks launch (and fill
    // their cp.async pipelines) while qw_kernel is still running.
    cudaLaunchConfig_t cfg = {};
    cfg.gridDim  = dim3(BT, 1, 1);
    cfg.blockDim = dim3(256, 1, 1);
    cfg.dynamicSmemBytes = SMEM_BYTES;
    cfg.stream = 0;
    cudaLaunchAttribute attr[1];
    attr[0].id = cudaLaunchAttributeProgrammaticStreamSerialization;
    attr[0].val.programmaticStreamSerializationAllowed = 1;
    cfg.attrs = attr;
    cfg.numAttrs = 1;

    cudaError_t e = cudaLaunchKernelEx(&cfg, kb_main_kernel,
                                       Q, K_kb, V_kb, ctx, b_ctx, rel, ent,
                                       qmin, qmax, tmin, tmax, rid, eid,
                                       out_alpha, out_v);
    if (e != cudaSuccess) {
        // Fallback: plain serialized launch (cudaGridDependencySynchronize is
        // a no-op when the dependency is already satisfied at block start).
        kb_main_kernel<<<BT, 256, SMEM_BYTES>>>(Q, K_kb, V_kb, ctx, b_ctx,
                                                rel, ent, qmin, qmax,
                                                tmin, tmax, rid, eid,
                                                out_alpha, out_v);
    }
}